// round 3
// baseline (speedup 1.0000x reference)
#include <cuda_runtime.h>
#include <cuda_fp16.h>
#include <cstdint>

// ============================================================================
// interactionModule_nonParametric_torque: per-edge MLP (4->128->128->128->1)
// + segment-mean over dst + node velocity.
//
// compute_100 target (no tcgen05) -> classic mma.sync m16n8k16 HMMA.
// Each warp owns a tile of 16 edges. Activations stay in registers as mma
// C-fragments; C-fragment layout == next layer's A-fragment layout
// (register-local relayout). Weights pre-arranged in SMEM in B-fragment
// order -> one conflict-free LDS.64 per mma.
// ============================================================================

#define H 128
#define NMAX 50000
#define NWARPS 4            // warps per CTA

__device__ float g_sums[NMAX];
__device__ int   g_cnt[NMAX];

// ---- SMEM layout (bytes) ----
static constexpr int OFF_WB0  = 0;          // 16 j * 32 lanes * 8B      = 4096
static constexpr int OFF_WB1  = 4096;       // 16*8*32*8                 = 32768
static constexpr int OFF_WB2  = 36864;      // 32768
static constexpr int OFF_B0F2 = 69632;      // 16*32*8                   = 4096
static constexpr int OFF_B1F2 = 73728;      // 4096
static constexpr int OFF_B2F2 = 77824;      // 4096
static constexpr int OFF_W3F2 = 81920;      // 4096
static constexpr int OFF_FEAT = 86016;      // NWARPS * 16*16 halves     = 2048
static constexpr int FEAT_BYTES = NWARPS * 16 * 16 * 2;
static constexpr int SMEM_TOTAL = OFF_FEAT + FEAT_BYTES;   // 88064 B

__device__ __forceinline__ void mma16816(float& c0, float& c1, float& c2, float& c3,
                                         uint32_t a0, uint32_t a1, uint32_t a2, uint32_t a3,
                                         uint32_t b0, uint32_t b1) {
    asm volatile(
        "mma.sync.aligned.m16n8k16.row.col.f32.f16.f16.f32 "
        "{%0,%1,%2,%3},{%4,%5,%6,%7},{%8,%9},{%0,%1,%2,%3};"
        : "+f"(c0), "+f"(c1), "+f"(c2), "+f"(c3)
        : "r"(a0), "r"(a1), "r"(a2), "r"(a3), "r"(b0), "r"(b1));
}

__device__ __forceinline__ uint32_t pack_h2(float lo, float hi) {
    __half2 h = __floats2half2_rn(lo, hi);
    return *reinterpret_cast<uint32_t*>(&h);
}

// One hidden layer: acc[16][4] (f32 C-frags, 16 n-tiles) = A(a-frags) @ W(SMEM)
__device__ __forceinline__ void layer128(float acc[16][4], const uint32_t a[8][4],
                                         const uint2* __restrict__ wb, int lane) {
    #pragma unroll
    for (int j = 0; j < 16; j++) {
        float c0 = 0.f, c1 = 0.f, c2 = 0.f, c3 = 0.f;
        #pragma unroll
        for (int ks = 0; ks < 8; ks++) {
            uint2 b = wb[(j * 8 + ks) * 32 + lane];
            mma16816(c0, c1, c2, c3, a[ks][0], a[ks][1], a[ks][2], a[ks][3], b.x, b.y);
        }
        acc[j][0] = c0; acc[j][1] = c1; acc[j][2] = c2; acc[j][3] = c3;
    }
}

// bias + ReLU + f32->f16, register-local C-frag -> A-frag relayout
__device__ __forceinline__ void convert(const float acc[16][4],
                                        const float2* __restrict__ biasf2,
                                        int lane, uint32_t a[8][4]) {
    #pragma unroll
    for (int j = 0; j < 16; j++) {
        float2 bv = biasf2[j * 32 + lane];
        float v0 = fmaxf(acc[j][0] + bv.x, 0.f);
        float v1 = fmaxf(acc[j][1] + bv.y, 0.f);
        float v2 = fmaxf(acc[j][2] + bv.x, 0.f);
        float v3 = fmaxf(acc[j][3] + bv.y, 0.f);
        int ks = j >> 1, h = j & 1;
        a[ks][2 * h + 0] = pack_h2(v0, v1);
        a[ks][2 * h + 1] = pack_h2(v2, v3);
    }
}

extern "C" __global__ void __launch_bounds__(NWARPS * 32, 2)
gnn_main(const float* __restrict__ x, const float* __restrict__ theta,
         const float* __restrict__ W0, const float* __restrict__ b0,
         const float* __restrict__ W1, const float* __restrict__ b1,
         const float* __restrict__ W2, const float* __restrict__ b2,
         const float* __restrict__ W3, const float* __restrict__ b3,
         const int* __restrict__ src, const int* __restrict__ dst,
         int E, int nWT) {
    extern __shared__ char smem[];
    const int nThr = NWARPS * 32;
    int tid = threadIdx.x;
    int lane = tid & 31;
    int warp = tid >> 5;
    int g = lane >> 2;     // row group 0..7
    int tig = lane & 3;    // thread-in-group

    uint2*  wb0    = (uint2*) (smem + OFF_WB0);
    uint2*  wb1    = (uint2*) (smem + OFF_WB1);
    uint2*  wb2    = (uint2*) (smem + OFF_WB2);
    float2* b0f2   = (float2*)(smem + OFF_B0F2);
    float2* b1f2   = (float2*)(smem + OFF_B1F2);
    float2* b2f2   = (float2*)(smem + OFF_B2F2);
    float2* w3f2   = (float2*)(smem + OFF_W3F2);
    __half* featAll= (__half*)(smem + OFF_FEAT);

    // ---- stage weights in B-fragment order (once per CTA) ----
    // wb0: layer0 (K padded 4->16). frag rows k0,k0+1 (k0=2*tt), rows +8 pad
    for (int i = tid; i < 16 * 32; i += nThr) {
        int jj = i >> 5, ll = i & 31;
        int gg = ll >> 2, tt = ll & 3;
        int c = 8 * jj + gg;
        int k0 = 2 * tt;
        __half h0 = (k0     < 4) ? __float2half_rn(W0[(k0    ) * H + c]) : __half(0.f);
        __half h1 = (k0 + 1 < 4) ? __float2half_rn(W0[(k0 + 1) * H + c]) : __half(0.f);
        uint2 u;
        u.x = ((uint32_t)__half_as_ushort(h0)) | ((uint32_t)__half_as_ushort(h1) << 16);
        u.y = 0u;   // rows k0+8, k0+9 are always padding
        wb0[i] = u;
    }
    // wb1/wb2: 16 n-tiles x 8 k-steps x 32 lanes
    for (int i = tid; i < 16 * 8 * 32; i += nThr) {
        int ll = i & 31;
        int ks = (i >> 5) & 7;
        int jj = i >> 8;
        int gg = ll >> 2, tt = ll & 3;
        int c = 8 * jj + gg;
        int k0 = 16 * ks + 2 * tt;
        uint2 u1, u2;
        u1.x = pack_h2(W1[(k0    ) * H + c], W1[(k0 + 1) * H + c]);
        u1.y = pack_h2(W1[(k0 + 8) * H + c], W1[(k0 + 9) * H + c]);
        u2.x = pack_h2(W2[(k0    ) * H + c], W2[(k0 + 1) * H + c]);
        u2.y = pack_h2(W2[(k0 + 8) * H + c], W2[(k0 + 9) * H + c]);
        wb1[i] = u1;
        wb2[i] = u2;
    }
    // biases + W3 as per-(n-tile,lane) float2
    for (int i = tid; i < 16 * 32; i += nThr) {
        int jj = i >> 5, tt = i & 3;
        int c = 8 * jj + 2 * tt;
        b0f2[i] = make_float2(b0[c], b0[c + 1]);
        b1f2[i] = make_float2(b1[c], b1[c + 1]);
        b2f2[i] = make_float2(b2[c], b2[c + 1]);
        w3f2[i] = make_float2(W3[c], W3[c + 1]);
    }
    // zero the feature staging buffers (cols 4..15 must stay zero forever)
    for (int i = tid; i < FEAT_BYTES / 4; i += nThr)
        reinterpret_cast<uint32_t*>(featAll)[i] = 0u;
    __syncthreads();

    float b3v = b3[0];
    __half* fb = featAll + warp * 256;   // 16 rows x 16 halves per warp

    int warpsTotal = gridDim.x * NWARPS;
    int wgid = blockIdx.x * NWARPS + warp;

    for (int t = wgid; t < nWT; t += warpsTotal) {
        int e = t * 16 + lane;
        int dn = -1;

        // ---- per-edge feature (lanes 0..15) ----
        if (lane < 16) {
            float f0 = 0.f, f1 = 0.f, f2 = 0.f, f3 = 0.f;
            if (e < E) {
                int sN = src[e], dN = dst[e];
                float drx = x[2 * dN]     - x[2 * sN];
                float dry = x[2 * dN + 1] - x[2 * sN + 1];
                float ts = theta[sN], td = theta[dN];
                float ss, cs; sincosf(ts, &ss, &cs);
                float sdt, cdt; sincosf(td - ts, &sdt, &cdt);
                f0 =  drx * cs + dry * ss;
                f1 = -drx * ss + dry * cs;
                f2 = cdt;
                f3 = sdt;
                dn = dN;
            }
            uint32_t* row = reinterpret_cast<uint32_t*>(fb + lane * 16);
            row[0] = pack_h2(f0, f1);
            row[1] = pack_h2(f2, f3);
        }
        __syncwarp();

        // A0 fragment from SMEM (cols >= 4 are zeros by construction)
        uint32_t ra0 = *reinterpret_cast<const uint32_t*>(fb + g * 16 + 2 * tig);
        uint32_t ra1 = *reinterpret_cast<const uint32_t*>(fb + (g + 8) * 16 + 2 * tig);
        __syncwarp();   // reads done before next iteration's writes

        float acc[16][4];
        // ---- L0: single k-step ----
        #pragma unroll
        for (int j = 0; j < 16; j++) {
            float c0 = 0.f, c1 = 0.f, c2 = 0.f, c3 = 0.f;
            uint2 b = wb0[j * 32 + lane];
            mma16816(c0, c1, c2, c3, ra0, ra1, 0u, 0u, b.x, b.y);
            acc[j][0] = c0; acc[j][1] = c1; acc[j][2] = c2; acc[j][3] = c3;
        }

        uint32_t a[8][4];
        convert(acc, b0f2, lane, a);   // relu(.+b0) -> A1
        layer128(acc, a, wb1, lane);   // L1
        convert(acc, b1f2, lane, a);   // relu(.+b1) -> A2
        layer128(acc, a, wb2, lane);   // L2

        // ---- final layer + reduce: m = sum_j relu(h+b2)*W3 + b3 ----
        float plo = 0.f, phi = 0.f;
        #pragma unroll
        for (int j = 0; j < 16; j++) {
            float2 bv = b2f2[j * 32 + lane];
            float2 wv = w3f2[j * 32 + lane];
            plo += fmaxf(acc[j][0] + bv.x, 0.f) * wv.x
                 + fmaxf(acc[j][1] + bv.y, 0.f) * wv.y;
            phi += fmaxf(acc[j][2] + bv.x, 0.f) * wv.x
                 + fmaxf(acc[j][3] + bv.y, 0.f) * wv.y;
        }
        // reduce across the 4 lanes of each row-group
        plo += __shfl_xor_sync(0xffffffffu, plo, 1);
        plo += __shfl_xor_sync(0xffffffffu, plo, 2);
        phi += __shfl_xor_sync(0xffffffffu, phi, 1);
        phi += __shfl_xor_sync(0xffffffffu, phi, 2);
        int dlo = __shfl_sync(0xffffffffu, dn, g);
        int dhi = __shfl_sync(0xffffffffu, dn, g + 8);
        if (tig == 0) {
            if (dlo >= 0) {
                atomicAdd(&g_sums[dlo], plo + b3v);
                atomicAdd(&g_cnt[dlo], 1);
            }
            if (dhi >= 0) {
                atomicAdd(&g_sums[dhi], phi + b3v);
                atomicAdd(&g_cnt[dhi], 1);
            }
        }
    }
}

// ---------------- aux kernels ----------------
extern "C" __global__ void k_zero(int n) {
    int i = blockIdx.x * blockDim.x + threadIdx.x;
    if (i < n) { g_sums[i] = 0.f; g_cnt[i] = 0; }
}

extern "C" __global__ void k_final(const float* __restrict__ theta,
                                   const float* __restrict__ v0p,
                                   float* __restrict__ out, int n) {
    int i = blockIdx.x * blockDim.x + threadIdx.x;
    if (i < n) {
        float v0 = v0p[0];
        float s, c; sincosf(theta[i], &s, &c);
        out[2 * i]     = v0 * c;
        out[2 * i + 1] = v0 * s;
        out[2 * n + i] = g_sums[i] / fmaxf((float)g_cnt[i], 1.f);
    }
}

// ---------------- launch ----------------
extern "C" void kernel_launch(void* const* d_in, const int* in_sizes, int n_in,
                              void* d_out, int out_size) {
    const float* x     = (const float*)d_in[0];
    const float* theta = (const float*)d_in[1];
    const float* v0    = (const float*)d_in[2];
    const float* W0    = (const float*)d_in[3];
    const float* b0    = (const float*)d_in[4];
    const float* W1    = (const float*)d_in[5];
    const float* b1    = (const float*)d_in[6];
    const float* W2    = (const float*)d_in[7];
    const float* b2    = (const float*)d_in[8];
    const float* W3    = (const float*)d_in[9];
    const float* b3    = (const float*)d_in[10];
    const int*   src   = (const int*)d_in[11];
    const int*   dst   = (const int*)d_in[12];

    int N = in_sizes[1];    // theta element count
    int E = in_sizes[11];   // src element count
    float* out = (float*)d_out;

    cudaFuncSetAttribute(gnn_main, cudaFuncAttributeMaxDynamicSharedMemorySize, SMEM_TOTAL);

    k_zero<<<(N + 255) / 256, 256>>>(N);

    int nWT = (E + 15) / 16;
    int grid = 296;   // 2 CTAs per SM on 148 SMs
    if (grid * NWARPS > nWT) grid = (nWT + NWARPS - 1) / NWARPS;
    gnn_main<<<grid, NWARPS * 32, SMEM_TOTAL>>>(x, theta, W0, b0, W1, b1, W2, b2, W3, b3,
                                                src, dst, E, nWT);

    k_final<<<(N + 255) / 256, 256>>>(theta, v0, out, N);
}